// round 4
// baseline (speedup 1.0000x reference)
#include <cuda_runtime.h>
#include <cuda_bf16.h>
#include <math.h>

#define HID 128
#define MAX_N 100000

// Scratch (device globals: no allocation allowed in kernel_launch)
__device__ __align__(16) float g_h[MAX_N * HID];     // relu(x) @ W
__device__ __align__(16) float g_agg[MAX_N * HID];   // aggregated messages
__device__ int   g_deg[MAX_N];
__device__ float g_dinv[MAX_N];
__device__ __align__(16) float g_colsum[HID];
__device__ __align__(16) float g_colsq[HID];
__device__ __align__(16) float g_scale[HID];
__device__ __align__(16) float g_shift[HID];

// ---------------------------------------------------------------------------
// 1) init: deg = 1 (self loop), zero column accumulators
__global__ void kk_init(int n) {
    int i = blockIdx.x * blockDim.x + threadIdx.x;
    if (i < n) g_deg[i] = 1;
    if (i < HID) { g_colsum[i] = 0.f; g_colsq[i] = 0.f; }
}

// 2) degree count from target nodes (edge_index is int32!)
__global__ void kk_deg(const int* __restrict__ col, int e) {
    int i = blockIdx.x * blockDim.x + threadIdx.x;
    if (i < e) atomicAdd(&g_deg[col[i]], 1);
}

// 3) dinv = deg^{-1/2}
__global__ void kk_dinv(int n) {
    int i = blockIdx.x * blockDim.x + threadIdx.x;
    if (i < n) g_dinv[i] = rsqrtf((float)g_deg[i]);
}

// ---------------------------------------------------------------------------
// 4) h = relu(x) @ W, agg initialized with self-loop term dinv^2 * h.
//    128 threads/block; thread t owns output column t and holds W[:,t] in
//    registers (128 floats). 8 rows per iteration staged through 4KB smem.
__global__ void __launch_bounds__(128, 1)
kk_gemm(const float* __restrict__ x, const float* __restrict__ W, int n) {
    __shared__ float sx[8][HID];
    int t = threadIdx.x;  // 0..127

    float w[HID];
    #pragma unroll
    for (int k = 0; k < HID; k++) w[k] = W[k * HID + t];  // coalesced per k

    for (int row0 = blockIdx.x * 8; row0 < n; row0 += gridDim.x * 8) {
        int rmax = min(8, n - row0);
        for (int r = 0; r < rmax; r++)
            sx[r][t] = fmaxf(x[(size_t)(row0 + r) * HID + t], 0.f);
        __syncthreads();

        float acc[8];
        #pragma unroll
        for (int r = 0; r < 8; r++) acc[r] = 0.f;

        #pragma unroll
        for (int k = 0; k < HID; k += 4) {
            #pragma unroll
            for (int r = 0; r < 8; r++) {
                float4 xv = *(const float4*)&sx[r][k];
                acc[r] = fmaf(xv.x, w[k + 0], acc[r]);
                acc[r] = fmaf(xv.y, w[k + 1], acc[r]);
                acc[r] = fmaf(xv.z, w[k + 2], acc[r]);
                acc[r] = fmaf(xv.w, w[k + 3], acc[r]);
            }
        }
        for (int r = 0; r < rmax; r++) {
            int row = row0 + r;
            float d = g_dinv[row];
            g_h[(size_t)row * HID + t] = acc[r];
            g_agg[(size_t)row * HID + t] = d * d * acc[r];  // self-loop term
        }
        __syncthreads();
    }
}

// ---------------------------------------------------------------------------
// 5) edge aggregation: one warp per edge, lane owns 4 consecutive floats.
//    agg[col] += dinv[row]*dinv[col] * h[row]  (scalar float atomics)
__global__ void kk_edge(const int* __restrict__ rows,
                        const int* __restrict__ cols, int e) {
    int idx = blockIdx.x * blockDim.x + threadIdx.x;
    int warp = idx >> 5;
    int lane = idx & 31;
    if (warp >= e) return;
    int r = rows[warp];
    int c = cols[warp];
    float nrm = g_dinv[r] * g_dinv[c];
    const float* src = g_h + (size_t)r * HID + lane * 4;
    float4 v = *(const float4*)src;
    float* dst = g_agg + (size_t)c * HID + lane * 4;
    atomicAdd(dst + 0, v.x * nrm);
    atomicAdd(dst + 1, v.y * nrm);
    atomicAdd(dst + 2, v.z * nrm);
    atomicAdd(dst + 3, v.w * nrm);
}

// ---------------------------------------------------------------------------
// 6) column stats: sum and sum-of-squares of agg (conv bias b cancels in BN).
__global__ void kk_stats(int n) {
    int t = threadIdx.x;
    int c4 = t & 31;   // float4 column group
    int ro = t >> 5;   // 8 row-lanes
    float4 s = make_float4(0.f, 0.f, 0.f, 0.f);
    float4 q = make_float4(0.f, 0.f, 0.f, 0.f);
    const float4* a4 = (const float4*)g_agg;
    for (int row = blockIdx.x * 8 + ro; row < n; row += gridDim.x * 8) {
        float4 v = a4[(size_t)row * 32 + c4];
        s.x += v.x; s.y += v.y; s.z += v.z; s.w += v.w;
        q.x += v.x * v.x; q.y += v.y * v.y; q.z += v.z * v.z; q.w += v.w * v.w;
    }
    __shared__ float4 ssum[256], ssq[256];
    ssum[t] = s; ssq[t] = q;
    __syncthreads();
    for (int step = 4; step >= 1; step >>= 1) {
        if (ro < step) {
            float4 a = ssum[t], b = ssum[t + step * 32];
            a.x += b.x; a.y += b.y; a.z += b.z; a.w += b.w; ssum[t] = a;
            float4 c = ssq[t], d = ssq[t + step * 32];
            c.x += d.x; c.y += d.y; c.z += d.z; c.w += d.w; ssq[t] = c;
        }
        __syncthreads();
    }
    if (ro == 0) {
        float4 a = ssum[t], c = ssq[t];
        atomicAdd(&g_colsum[c4 * 4 + 0], a.x);
        atomicAdd(&g_colsum[c4 * 4 + 1], a.y);
        atomicAdd(&g_colsum[c4 * 4 + 2], a.z);
        atomicAdd(&g_colsum[c4 * 4 + 3], a.w);
        atomicAdd(&g_colsq[c4 * 4 + 0], c.x);
        atomicAdd(&g_colsq[c4 * 4 + 1], c.y);
        atomicAdd(&g_colsq[c4 * 4 + 2], c.z);
        atomicAdd(&g_colsq[c4 * 4 + 3], c.w);
    }
}

// 7) finalize BN coefficients (out = sc*(agg - mean_agg) + beta; b cancels)
__global__ void kk_finstats(const float* __restrict__ gamma,
                            const float* __restrict__ beta, float inv_n) {
    int c = threadIdx.x;
    float mean = g_colsum[c] * inv_n;
    float var = g_colsq[c] * inv_n - mean * mean;
    float sc = gamma[c] * rsqrtf(var + 1e-5f);
    g_scale[c] = sc;
    g_shift[c] = beta[c] - sc * mean;
}

// 8) out = scale[c]*agg + shift[c]
__global__ void kk_out(float* __restrict__ out, int n) {
    size_t i = (size_t)blockIdx.x * blockDim.x + threadIdx.x;
    if (i >= (size_t)n * 32) return;
    int c4 = (int)(i & 31);
    float4 v = ((const float4*)g_agg)[i];
    float4 sc = ((const float4*)g_scale)[c4];
    float4 sh = ((const float4*)g_shift)[c4];
    v.x = fmaf(v.x, sc.x, sh.x);
    v.y = fmaf(v.y, sc.y, sh.y);
    v.z = fmaf(v.z, sc.z, sh.z);
    v.w = fmaf(v.w, sc.w, sh.w);
    ((float4*)out)[i] = v;
}

// ---------------------------------------------------------------------------
extern "C" void kernel_launch(void* const* d_in, const int* in_sizes, int n_in,
                              void* d_out, int out_size) {
    const float* x = (const float*)d_in[0];
    const int* ei = (const int*)d_in[1];          // int32 (JAX x64 disabled)
    const float* W = (const float*)d_in[2];
    // d_in[3] = b (cancels inside BatchNorm, unused)
    const float* gamma = (const float*)d_in[4];
    const float* beta = (const float*)d_in[5];
    float* out = (float*)d_out;

    int n = in_sizes[0] / HID;
    int e = in_sizes[1] / 2;
    const int* erow = ei;       // sources
    const int* ecol = ei + e;   // targets

    kk_init<<<(n + 255) / 256, 256>>>(n);
    kk_deg<<<(e + 255) / 256, 256>>>(ecol, e);
    kk_dinv<<<(n + 255) / 256, 256>>>(n);

    {
        int need = (n + 7) / 8;
        int blocks = need < 592 ? need : 592;  // ~4 blocks/SM persistent
        kk_gemm<<<blocks, HID>>>(x, W, n);
    }

    kk_edge<<<(e + 7) / 8, 256>>>(erow, ecol, e);

    kk_stats<<<1024, 256>>>(n);
    kk_finstats<<<1, HID>>>(gamma, beta, 1.0f / (float)n);

    {
        size_t total = (size_t)n * 32;
        kk_out<<<(int)((total + 255) / 256), 256>>>(out, n);
    }
}

// round 5
// speedup vs baseline: 1.5125x; 1.5125x over previous
#include <cuda_runtime.h>
#include <cuda_bf16.h>
#include <math.h>

#define HID 128
#define MAX_N 100000
#define TR 32   // rows per GEMM tile

// Scratch (device globals: no allocation allowed in kernel_launch)
__device__ __align__(16) float g_h[MAX_N * HID];     // relu(x) @ W
__device__ __align__(16) float g_agg[MAX_N * HID];   // aggregated messages
__device__ int   g_deg[MAX_N];
__device__ float g_dinv[MAX_N];
__device__ __align__(16) float g_colsum[HID];
__device__ __align__(16) float g_colsq[HID];
__device__ __align__(16) float g_scale[HID];
__device__ __align__(16) float g_shift[HID];

// ---------------------------------------------------------------------------
// 1) init: deg = 1 (self loop), zero column accumulators
__global__ void kk_init(int n) {
    int i = blockIdx.x * blockDim.x + threadIdx.x;
    if (i < n) g_deg[i] = 1;
    if (i < HID) { g_colsum[i] = 0.f; g_colsq[i] = 0.f; }
}

// 2) degree count from target nodes (edge_index is int32)
__global__ void kk_deg(const int* __restrict__ col, int e) {
    int i = blockIdx.x * blockDim.x + threadIdx.x;
    if (i < e) atomicAdd(&g_deg[col[i]], 1);
}

// 3) dinv = deg^{-1/2}
__global__ void kk_dinv(int n) {
    int i = blockIdx.x * blockDim.x + threadIdx.x;
    if (i < n) g_dinv[i] = rsqrtf((float)g_deg[i]);
}

// ---------------------------------------------------------------------------
// 4) h = relu(x) @ W, agg initialized with self-loop term dinv^2 * h.
//    Register-blocked: 128 threads, tile 32 rows x 128 cols.
//    Thread (cg = t&31, rg = t>>5) computes rows rg*8..rg*8+7, cols cg*4..cg*4+3
//    => 32 accumulators; per k: 1 LDS.128 (W) + 8 broadcast LDS (x) feed 32 FMA.
__global__ void __launch_bounds__(128, 2)
kk_gemm(const float* __restrict__ x, const float* __restrict__ W, int n) {
    extern __shared__ float sm[];
    float* sW = sm;              // [128][128] = 64KB
    float* sx = sm + HID * HID;  // [TR][128]  = 16KB (row-major)

    int t = threadIdx.x;
    int cg = t & 31;   // column group (4 cols)
    int rg = t >> 5;   // row group (8 rows)

    // Load W (coalesced float4)
    for (int i = t * 4; i < HID * HID; i += 128 * 4)
        *(float4*)&sW[i] = *(const float4*)&W[i];
    __syncthreads();

    for (int row0 = blockIdx.x * TR; row0 < n; row0 += gridDim.x * TR) {
        int rmax = min(TR, n - row0);
        // Load x tile with ReLU; thread loads float4 j = r*32 + k4
        for (int j = t; j < TR * 32; j += 128) {
            int r = j >> 5, k4 = j & 31;
            float4 v;
            if (r < rmax) {
                v = *(const float4*)&x[(size_t)(row0 + r) * HID + k4 * 4];
                v.x = fmaxf(v.x, 0.f); v.y = fmaxf(v.y, 0.f);
                v.z = fmaxf(v.z, 0.f); v.w = fmaxf(v.w, 0.f);
            } else {
                v = make_float4(0.f, 0.f, 0.f, 0.f);
            }
            *(float4*)&sx[r * HID + k4 * 4] = v;   // STS.128 conflict-free
        }
        __syncthreads();

        float acc[8][4];
        #pragma unroll
        for (int i = 0; i < 8; i++)
            #pragma unroll
            for (int j = 0; j < 4; j++) acc[i][j] = 0.f;

        #pragma unroll 2
        for (int k = 0; k < HID; k++) {
            float4 wv = *(const float4*)&sW[k * HID + cg * 4];
            float xr[8];
            #pragma unroll
            for (int i = 0; i < 8; i++)
                xr[i] = sx[(rg * 8 + i) * HID + k];   // warp broadcast
            #pragma unroll
            for (int i = 0; i < 8; i++) {
                acc[i][0] = fmaf(xr[i], wv.x, acc[i][0]);
                acc[i][1] = fmaf(xr[i], wv.y, acc[i][1]);
                acc[i][2] = fmaf(xr[i], wv.z, acc[i][2]);
                acc[i][3] = fmaf(xr[i], wv.w, acc[i][3]);
            }
        }

        #pragma unroll
        for (int i = 0; i < 8; i++) {
            int r = rg * 8 + i;
            if (r < rmax) {
                int row = row0 + r;
                float d = g_dinv[row];
                float d2 = d * d;
                float4 hv = make_float4(acc[i][0], acc[i][1], acc[i][2], acc[i][3]);
                *(float4*)&g_h[(size_t)row * HID + cg * 4] = hv;
                float4 av = make_float4(hv.x * d2, hv.y * d2, hv.z * d2, hv.w * d2);
                *(float4*)&g_agg[(size_t)row * HID + cg * 4] = av;  // self-loop
            }
        }
        __syncthreads();
    }
}

// ---------------------------------------------------------------------------
// 5) edge aggregation: one warp per edge, lane owns 4 consecutive floats.
//    agg[col] += dinv[row]*dinv[col] * h[row]  via vector float4 atomicAdd.
__global__ void kk_edge(const int* __restrict__ rows,
                        const int* __restrict__ cols, int e) {
    int idx = blockIdx.x * blockDim.x + threadIdx.x;
    int warp = idx >> 5;
    int lane = idx & 31;
    if (warp >= e) return;
    int r = rows[warp];
    int c = cols[warp];
    float nrm = g_dinv[r] * g_dinv[c];
    float4 v = *((const float4*)(g_h + (size_t)r * HID) + lane);
    v.x *= nrm; v.y *= nrm; v.z *= nrm; v.w *= nrm;
    atomicAdd((float4*)(g_agg + (size_t)c * HID) + lane, v);
}

// ---------------------------------------------------------------------------
// 6) column stats: sum and sum-of-squares of agg (conv bias b cancels in BN).
__global__ void kk_stats(int n) {
    int t = threadIdx.x;
    int c4 = t & 31;   // float4 column group
    int ro = t >> 5;   // 8 row-lanes
    float4 s = make_float4(0.f, 0.f, 0.f, 0.f);
    float4 q = make_float4(0.f, 0.f, 0.f, 0.f);
    const float4* a4 = (const float4*)g_agg;
    for (int row = blockIdx.x * 8 + ro; row < n; row += gridDim.x * 8) {
        float4 v = a4[(size_t)row * 32 + c4];
        s.x += v.x; s.y += v.y; s.z += v.z; s.w += v.w;
        q.x += v.x * v.x; q.y += v.y * v.y; q.z += v.z * v.z; q.w += v.w * v.w;
    }
    __shared__ float4 ssum[256], ssq[256];
    ssum[t] = s; ssq[t] = q;
    __syncthreads();
    for (int step = 4; step >= 1; step >>= 1) {
        if (ro < step) {
            float4 a = ssum[t], b = ssum[t + step * 32];
            a.x += b.x; a.y += b.y; a.z += b.z; a.w += b.w; ssum[t] = a;
            float4 c = ssq[t], d = ssq[t + step * 32];
            c.x += d.x; c.y += d.y; c.z += d.z; c.w += d.w; ssq[t] = c;
        }
        __syncthreads();
    }
    if (ro == 0) {
        float4 a = ssum[t], c = ssq[t];
        atomicAdd(&g_colsum[c4 * 4 + 0], a.x);
        atomicAdd(&g_colsum[c4 * 4 + 1], a.y);
        atomicAdd(&g_colsum[c4 * 4 + 2], a.z);
        atomicAdd(&g_colsum[c4 * 4 + 3], a.w);
        atomicAdd(&g_colsq[c4 * 4 + 0], c.x);
        atomicAdd(&g_colsq[c4 * 4 + 1], c.y);
        atomicAdd(&g_colsq[c4 * 4 + 2], c.z);
        atomicAdd(&g_colsq[c4 * 4 + 3], c.w);
    }
}

// 7) finalize BN coefficients (out = sc*(agg - mean_agg) + beta; b cancels)
__global__ void kk_finstats(const float* __restrict__ gamma,
                            const float* __restrict__ beta, float inv_n) {
    int c = threadIdx.x;
    float mean = g_colsum[c] * inv_n;
    float var = g_colsq[c] * inv_n - mean * mean;
    float sc = gamma[c] * rsqrtf(var + 1e-5f);
    g_scale[c] = sc;
    g_shift[c] = beta[c] - sc * mean;
}

// 8) out = scale[c]*agg + shift[c]
__global__ void kk_out(float* __restrict__ out, int n) {
    size_t i = (size_t)blockIdx.x * blockDim.x + threadIdx.x;
    if (i >= (size_t)n * 32) return;
    int c4 = (int)(i & 31);
    float4 v = ((const float4*)g_agg)[i];
    float4 sc = ((const float4*)g_scale)[c4];
    float4 sh = ((const float4*)g_shift)[c4];
    v.x = fmaf(v.x, sc.x, sh.x);
    v.y = fmaf(v.y, sc.y, sh.y);
    v.z = fmaf(v.z, sc.z, sh.z);
    v.w = fmaf(v.w, sc.w, sh.w);
    ((float4*)out)[i] = v;
}

// ---------------------------------------------------------------------------
extern "C" void kernel_launch(void* const* d_in, const int* in_sizes, int n_in,
                              void* d_out, int out_size) {
    const float* x = (const float*)d_in[0];
    const int* ei = (const int*)d_in[1];          // int32 (JAX x64 disabled)
    const float* W = (const float*)d_in[2];
    // d_in[3] = b (cancels inside BatchNorm, unused)
    const float* gamma = (const float*)d_in[4];
    const float* beta = (const float*)d_in[5];
    float* out = (float*)d_out;

    int n = in_sizes[0] / HID;
    int e = in_sizes[1] / 2;
    const int* erow = ei;       // sources
    const int* ecol = ei + e;   // targets

    kk_init<<<(n + 255) / 256, 256>>>(n);
    kk_deg<<<(e + 255) / 256, 256>>>(ecol, e);
    kk_dinv<<<(n + 255) / 256, 256>>>(n);

    {
        size_t smem = (size_t)(HID * HID + TR * HID) * sizeof(float);  // 80KB
        cudaFuncSetAttribute(kk_gemm, cudaFuncAttributeMaxDynamicSharedMemorySize,
                             (int)smem);
        int need = (n + TR - 1) / TR;
        int blocks = need < 296 ? need : 296;  // 2 blocks/SM persistent
        kk_gemm<<<blocks, 128, smem>>>(x, W, n);
    }

    kk_edge<<<(e + 7) / 8, 256>>>(erow, ecol, e);

    kk_stats<<<1024, 256>>>(n);
    kk_finstats<<<1, HID>>>(gamma, beta, 1.0f / (float)n);

    {
        size_t total = (size_t)n * 32;
        kk_out<<<(int)((total + 255) / 256), 256>>>(out, n);
    }
}

// round 6
// speedup vs baseline: 1.8668x; 1.2343x over previous
#include <cuda_runtime.h>
#include <cuda_bf16.h>
#include <math.h>

#define HID 128
#define MAX_N 100000
#define MAX_E 600000
#define TR 32           // rows per GEMM tile
#define SCAN_BS 256     // scan block size
#define MAX_SB 512      // max scan blocks (ceil(100000/256)=391)

// Scratch (device globals: no allocation allowed in kernel_launch)
__device__ __align__(16) float g_h[MAX_N * HID];     // relu(x) @ W
__device__ __align__(16) float g_agg[MAX_N * HID];   // aggregated messages
__device__ int   g_deg[MAX_N];       // in-degree (excluding self loop)
__device__ int   g_off[MAX_N];       // CSR offsets (exclusive prefix of deg)
__device__ int   g_cursor[MAX_N];    // scatter cursors
__device__ int   g_bsrc[MAX_E];      // bucketed source ids per destination
__device__ int   g_bsums[MAX_SB];    // scan block sums
__device__ float g_dinv[MAX_N];
__device__ __align__(16) float g_colsum[HID];
__device__ __align__(16) float g_colsq[HID];
__device__ __align__(16) float g_scale[HID];
__device__ __align__(16) float g_shift[HID];

// ---------------------------------------------------------------------------
// 1) init: zero deg/cursor, zero column accumulators
__global__ void kk_init(int n) {
    int i = blockIdx.x * blockDim.x + threadIdx.x;
    if (i < n) { g_deg[i] = 0; g_cursor[i] = 0; }
    if (i < HID) { g_colsum[i] = 0.f; g_colsq[i] = 0.f; }
}

// 2) in-degree count from target nodes (edge_index is int32)
__global__ void kk_deg(const int* __restrict__ col, int e) {
    int i = blockIdx.x * blockDim.x + threadIdx.x;
    if (i < e) atomicAdd(&g_deg[col[i]], 1);
}

// 3a) scan pass 1: per-block inclusive scan of deg; write exclusive to g_off,
//     block total to g_bsums. Also dinv = rsqrt(deg+1) (self loop included).
__global__ void kk_scan1(int n) {
    __shared__ int sd[SCAN_BS];
    int t = threadIdx.x;
    int idx = blockIdx.x * SCAN_BS + t;
    int v = (idx < n) ? g_deg[idx] : 0;
    if (idx < n) g_dinv[idx] = rsqrtf((float)(v + 1));
    sd[t] = v;
    __syncthreads();
    #pragma unroll
    for (int s = 1; s < SCAN_BS; s <<= 1) {
        int x = (t >= s) ? sd[t - s] : 0;
        __syncthreads();
        sd[t] += x;
        __syncthreads();
    }
    if (idx < n) g_off[idx] = sd[t] - v;           // exclusive within block
    if (t == SCAN_BS - 1) g_bsums[blockIdx.x] = sd[t];
}

// 3b) scan pass 2: single block scans block sums -> exclusive
__global__ void kk_scan2(int nb) {
    __shared__ int sd[MAX_SB];
    int t = threadIdx.x;   // 512 threads
    int v = (t < nb) ? g_bsums[t] : 0;
    sd[t] = v;
    __syncthreads();
    #pragma unroll
    for (int s = 1; s < MAX_SB; s <<= 1) {
        int x = (t >= s) ? sd[t - s] : 0;
        __syncthreads();
        sd[t] += x;
        __syncthreads();
    }
    if (t < nb) g_bsums[t] = sd[t] - v;            // exclusive
}

// 3c) scan pass 3: add block offsets
__global__ void kk_scan3(int n) {
    int idx = blockIdx.x * SCAN_BS + threadIdx.x;
    if (idx < n) g_off[idx] += g_bsums[blockIdx.x];
}

// 4) scatter edges into destination buckets (store source id)
__global__ void kk_scatter(const int* __restrict__ rows,
                           const int* __restrict__ cols, int e) {
    int i = blockIdx.x * blockDim.x + threadIdx.x;
    if (i >= e) return;
    int c = cols[i];
    int p = atomicAdd(&g_cursor[c], 1);
    g_bsrc[g_off[c] + p] = rows[i];
}

// ---------------------------------------------------------------------------
// 5) h = relu(x) @ W (register-blocked 32x128 tile, 128 threads)
__global__ void __launch_bounds__(128, 2)
kk_gemm(const float* __restrict__ x, const float* __restrict__ W, int n) {
    extern __shared__ float sm[];
    float* sW = sm;              // [128][128] = 64KB
    float* sx = sm + HID * HID;  // [TR][128]  = 16KB

    int t = threadIdx.x;
    int cg = t & 31;   // column group (4 cols)
    int rg = t >> 5;   // row group (8 rows)

    for (int i = t * 4; i < HID * HID; i += 128 * 4)
        *(float4*)&sW[i] = *(const float4*)&W[i];
    __syncthreads();

    for (int row0 = blockIdx.x * TR; row0 < n; row0 += gridDim.x * TR) {
        int rmax = min(TR, n - row0);
        for (int j = t; j < TR * 32; j += 128) {
            int r = j >> 5, k4 = j & 31;
            float4 v;
            if (r < rmax) {
                v = *(const float4*)&x[(size_t)(row0 + r) * HID + k4 * 4];
                v.x = fmaxf(v.x, 0.f); v.y = fmaxf(v.y, 0.f);
                v.z = fmaxf(v.z, 0.f); v.w = fmaxf(v.w, 0.f);
            } else {
                v = make_float4(0.f, 0.f, 0.f, 0.f);
            }
            *(float4*)&sx[r * HID + k4 * 4] = v;
        }
        __syncthreads();

        float acc[8][4];
        #pragma unroll
        for (int i = 0; i < 8; i++)
            #pragma unroll
            for (int j = 0; j < 4; j++) acc[i][j] = 0.f;

        #pragma unroll 2
        for (int k = 0; k < HID; k++) {
            float4 wv = *(const float4*)&sW[k * HID + cg * 4];
            float xr[8];
            #pragma unroll
            for (int i = 0; i < 8; i++)
                xr[i] = sx[(rg * 8 + i) * HID + k];
            #pragma unroll
            for (int i = 0; i < 8; i++) {
                acc[i][0] = fmaf(xr[i], wv.x, acc[i][0]);
                acc[i][1] = fmaf(xr[i], wv.y, acc[i][1]);
                acc[i][2] = fmaf(xr[i], wv.z, acc[i][2]);
                acc[i][3] = fmaf(xr[i], wv.w, acc[i][3]);
            }
        }

        #pragma unroll
        for (int i = 0; i < 8; i++) {
            int r = rg * 8 + i;
            if (r < rmax) {
                int row = row0 + r;
                *(float4*)&g_h[(size_t)row * HID + cg * 4] =
                    make_float4(acc[i][0], acc[i][1], acc[i][2], acc[i][3]);
            }
        }
        __syncthreads();
    }
}

// ---------------------------------------------------------------------------
// 6) destination-gather aggregation + fused BN stats.
//    One warp per node (grid-stride): acc = sum_e dinv[src]*h[src] (+ self),
//    agg = dinv[dst]*acc. No fp atomics on agg. Stats accumulated per warp.
__global__ void __launch_bounds__(256)
kk_aggstats(int n) {
    __shared__ float bsum[HID], bsq[HID];
    int t = threadIdx.x;
    int lane = t & 31;
    int w = t >> 5;
    if (t < HID) { bsum[t] = 0.f; bsq[t] = 0.f; }
    __syncthreads();

    int warp_id = blockIdx.x * 8 + w;
    int nwarps = gridDim.x * 8;

    float4 csum = make_float4(0.f, 0.f, 0.f, 0.f);
    float4 csq  = make_float4(0.f, 0.f, 0.f, 0.f);

    for (int node = warp_id; node < n; node += nwarps) {
        int start = g_off[node];
        int cnt   = g_deg[node];
        float dd  = g_dinv[node];

        // self-loop contribution: dd*h (final *dd gives dd^2*h)
        float4 h4 = ((const float4*)(g_h + (size_t)node * HID))[lane];
        float4 acc = make_float4(dd * h4.x, dd * h4.y, dd * h4.z, dd * h4.w);

        int j = 0;
        for (; j + 2 <= cnt; j += 2) {
            int s0 = g_bsrc[start + j];
            int s1 = g_bsrc[start + j + 1];
            float d0 = g_dinv[s0];
            float d1 = g_dinv[s1];
            float4 a = ((const float4*)(g_h + (size_t)s0 * HID))[lane];
            float4 b = ((const float4*)(g_h + (size_t)s1 * HID))[lane];
            acc.x += d0 * a.x + d1 * b.x;
            acc.y += d0 * a.y + d1 * b.y;
            acc.z += d0 * a.z + d1 * b.z;
            acc.w += d0 * a.w + d1 * b.w;
        }
        if (j < cnt) {
            int s0 = g_bsrc[start + j];
            float d0 = g_dinv[s0];
            float4 a = ((const float4*)(g_h + (size_t)s0 * HID))[lane];
            acc.x += d0 * a.x; acc.y += d0 * a.y;
            acc.z += d0 * a.z; acc.w += d0 * a.w;
        }

        float4 agg4 = make_float4(dd * acc.x, dd * acc.y, dd * acc.z, dd * acc.w);
        ((float4*)(g_agg + (size_t)node * HID))[lane] = agg4;

        csum.x += agg4.x; csum.y += agg4.y; csum.z += agg4.z; csum.w += agg4.w;
        csq.x += agg4.x * agg4.x; csq.y += agg4.y * agg4.y;
        csq.z += agg4.z * agg4.z; csq.w += agg4.w * agg4.w;
    }

    // merge warp accumulators into block smem (column c = lane*4+k)
    atomicAdd(&bsum[lane * 4 + 0], csum.x);
    atomicAdd(&bsum[lane * 4 + 1], csum.y);
    atomicAdd(&bsum[lane * 4 + 2], csum.z);
    atomicAdd(&bsum[lane * 4 + 3], csum.w);
    atomicAdd(&bsq[lane * 4 + 0], csq.x);
    atomicAdd(&bsq[lane * 4 + 1], csq.y);
    atomicAdd(&bsq[lane * 4 + 2], csq.z);
    atomicAdd(&bsq[lane * 4 + 3], csq.w);
    __syncthreads();
    if (t < HID) {
        atomicAdd(&g_colsum[t], bsum[t]);
        atomicAdd(&g_colsq[t], bsq[t]);
    }
}

// 7) finalize BN coefficients (out = sc*(agg - mean_agg) + beta; b cancels)
__global__ void kk_finstats(const float* __restrict__ gamma,
                            const float* __restrict__ beta, float inv_n) {
    int c = threadIdx.x;
    float mean = g_colsum[c] * inv_n;
    float var = g_colsq[c] * inv_n - mean * mean;
    float sc = gamma[c] * rsqrtf(var + 1e-5f);
    g_scale[c] = sc;
    g_shift[c] = beta[c] - sc * mean;
}

// 8) out = scale[c]*agg + shift[c]
__global__ void kk_out(float* __restrict__ out, int n) {
    size_t i = (size_t)blockIdx.x * blockDim.x + threadIdx.x;
    if (i >= (size_t)n * 32) return;
    int c4 = (int)(i & 31);
    float4 v = ((const float4*)g_agg)[i];
    float4 sc = ((const float4*)g_scale)[c4];
    float4 sh = ((const float4*)g_shift)[c4];
    v.x = fmaf(v.x, sc.x, sh.x);
    v.y = fmaf(v.y, sc.y, sh.y);
    v.z = fmaf(v.z, sc.z, sh.z);
    v.w = fmaf(v.w, sc.w, sh.w);
    ((float4*)out)[i] = v;
}

// ---------------------------------------------------------------------------
extern "C" void kernel_launch(void* const* d_in, const int* in_sizes, int n_in,
                              void* d_out, int out_size) {
    const float* x = (const float*)d_in[0];
    const int* ei = (const int*)d_in[1];          // int32 (JAX x64 disabled)
    const float* W = (const float*)d_in[2];
    // d_in[3] = b (cancels inside BatchNorm, unused)
    const float* gamma = (const float*)d_in[4];
    const float* beta = (const float*)d_in[5];
    float* out = (float*)d_out;

    int n = in_sizes[0] / HID;
    int e = in_sizes[1] / 2;
    const int* erow = ei;       // sources
    const int* ecol = ei + e;   // targets

    int nb = (n + SCAN_BS - 1) / SCAN_BS;

    kk_init<<<(n + 255) / 256, 256>>>(n);
    kk_deg<<<(e + 255) / 256, 256>>>(ecol, e);
    kk_scan1<<<nb, SCAN_BS>>>(n);
    kk_scan2<<<1, MAX_SB>>>(nb);
    kk_scan3<<<nb, SCAN_BS>>>(n);
    kk_scatter<<<(e + 255) / 256, 256>>>(erow, ecol, e);

    {
        size_t smem = (size_t)(HID * HID + TR * HID) * sizeof(float);  // 80KB
        cudaFuncSetAttribute(kk_gemm, cudaFuncAttributeMaxDynamicSharedMemorySize,
                             (int)smem);
        int need = (n + TR - 1) / TR;
        int blocks = need < 296 ? need : 296;  // 2 blocks/SM persistent
        kk_gemm<<<blocks, 128, smem>>>(x, W, n);
    }

    kk_aggstats<<<1184, 256>>>(n);   // 8 blocks/SM, warp per node grid-stride
    kk_finstats<<<1, HID>>>(gamma, beta, 1.0f / (float)n);

    {
        size_t total = (size_t)n * 32;
        kk_out<<<(int)((total + 255) / 256), 256>>>(out, n);
    }
}

// round 9
// speedup vs baseline: 2.5202x; 1.3500x over previous
#include <cuda_runtime.h>
#include <cuda_bf16.h>
#include <math.h>
#include <stdint.h>

#define HID 128
#define MAX_N 100000
#define MAX_E 600000
#define SCAN_BS 256
#define MAX_SB 512

// Scratch (device globals: no allocation allowed in kernel_launch)
__device__ __align__(16) float g_h[MAX_N * HID];     // relu(x) @ W
__device__ __align__(16) float g_agg[MAX_N * HID];   // aggregated messages
__device__ int   g_deg[MAX_N];
__device__ int   g_off[MAX_N];
__device__ int   g_cursor[MAX_N];
__device__ int   g_bsrc[MAX_E];
__device__ int   g_bsums[MAX_SB];
__device__ float g_dinv[MAX_N];
__device__ __align__(16) float g_colsum[HID];
__device__ __align__(16) float g_colsq[HID];
__device__ __align__(16) float g_scale[HID];
__device__ __align__(16) float g_shift[HID];

__device__ __forceinline__ uint32_t f2tf32(float f) {
    uint32_t r;
    asm("cvt.rna.tf32.f32 %0, %1;" : "=r"(r) : "f"(f));
    return r;
}

// ---------------------------------------------------------------------------
// 1) init
__global__ void kk_init(int n) {
    int i = blockIdx.x * blockDim.x + threadIdx.x;
    if (i < n) { g_deg[i] = 0; g_cursor[i] = 0; }
    if (i < HID) { g_colsum[i] = 0.f; g_colsq[i] = 0.f; }
}

// 2) in-degree from targets (edge_index is int32)
__global__ void kk_deg(const int* __restrict__ col, int e) {
    int i = blockIdx.x * blockDim.x + threadIdx.x;
    if (i < e) atomicAdd(&g_deg[col[i]], 1);
}

// 3a) per-block scan + dinv
__global__ void kk_scan1(int n) {
    __shared__ int sd[SCAN_BS];
    int t = threadIdx.x;
    int idx = blockIdx.x * SCAN_BS + t;
    int v = (idx < n) ? g_deg[idx] : 0;
    if (idx < n) g_dinv[idx] = rsqrtf((float)(v + 1));
    sd[t] = v;
    __syncthreads();
    #pragma unroll
    for (int s = 1; s < SCAN_BS; s <<= 1) {
        int x = (t >= s) ? sd[t - s] : 0;
        __syncthreads();
        sd[t] += x;
        __syncthreads();
    }
    if (idx < n) g_off[idx] = sd[t] - v;
    if (t == SCAN_BS - 1) g_bsums[blockIdx.x] = sd[t];
}
// 3b) scan block sums
__global__ void kk_scan2(int nb) {
    __shared__ int sd[MAX_SB];
    int t = threadIdx.x;
    int v = (t < nb) ? g_bsums[t] : 0;
    sd[t] = v;
    __syncthreads();
    #pragma unroll
    for (int s = 1; s < MAX_SB; s <<= 1) {
        int x = (t >= s) ? sd[t - s] : 0;
        __syncthreads();
        sd[t] += x;
        __syncthreads();
    }
    if (t < nb) g_bsums[t] = sd[t] - v;
}
// 3c) add block offsets
__global__ void kk_scan3(int n) {
    int idx = blockIdx.x * SCAN_BS + threadIdx.x;
    if (idx < n) g_off[idx] += g_bsums[blockIdx.x];
}
// 4) scatter edges into destination buckets
__global__ void kk_scatter(const int* __restrict__ rows,
                           const int* __restrict__ cols, int e) {
    int i = blockIdx.x * blockDim.x + threadIdx.x;
    if (i >= e) return;
    int c = cols[i];
    int p = atomicAdd(&g_cursor[c], 1);
    g_bsrc[g_off[c] + p] = rows[i];
}

// ---------------------------------------------------------------------------
// 5) h = relu(x) @ W via warp-level tf32 mma.sync (m16n8k8, fp32 accum).
//    Persistent CTAs: 128 threads (4 warps), tile = 64 rows x 128 cols.
//    Warp w owns rows w*16..w*16+15 (64 fp32 accumulators / lane).
//    smem (tf32 stored as 4B): sW = W^T [128 n][132], sA = x tile [64 r][132]
#define FSTRIDE 132            // floats per row (128 + 4 pad) = 528 B
#define SMW_BYTES (128 * FSTRIDE * 4)
#define SMA_BYTES (64 * FSTRIDE * 4)
#define SM_TOT (SMW_BYTES + SMA_BYTES)

__global__ void __launch_bounds__(128, 2)
kk_gemm(const float* __restrict__ x, const float* __restrict__ W, int n) {
    extern __shared__ uint32_t smem[];
    uint32_t* sW = smem;                       // [128][FSTRIDE]
    uint32_t* sA = smem + 128 * FSTRIDE;       // [64][FSTRIDE]

    int t = threadIdx.x;
    int w = t >> 5, lane = t & 31;
    int qr = lane >> 2;          // 0..7
    int qc = lane & 3;           // 0..3

    // Load W^T: sW[n=t][k] = tf32(W[k*128 + t])
    for (int k = 0; k < HID; k++)
        sW[t * FSTRIDE + k] = f2tf32(W[k * HID + t]);
    __syncthreads();

    for (int row0 = blockIdx.x * 64; row0 < n; row0 += gridDim.x * 64) {
        int rmax = min(64, n - row0);
        // load x tile -> sA tf32 with ReLU. 8 iters x 8 cols per thread
        #pragma unroll
        for (int it = 0; it < 8; it++) {
            int idx = t + it * 128;           // 0..1023
            int r = idx >> 4, c8 = idx & 15;  // r: 0..63, c8: 8-col chunk
            uint4 lo, hi;
            if (r < rmax) {
                const float4* src =
                    (const float4*)&x[(size_t)(row0 + r) * HID + c8 * 8];
                float4 a = src[0], b = src[1];
                lo = make_uint4(f2tf32(fmaxf(a.x, 0.f)), f2tf32(fmaxf(a.y, 0.f)),
                                f2tf32(fmaxf(a.z, 0.f)), f2tf32(fmaxf(a.w, 0.f)));
                hi = make_uint4(f2tf32(fmaxf(b.x, 0.f)), f2tf32(fmaxf(b.y, 0.f)),
                                f2tf32(fmaxf(b.z, 0.f)), f2tf32(fmaxf(b.w, 0.f)));
            } else {
                lo = make_uint4(0, 0, 0, 0);
                hi = make_uint4(0, 0, 0, 0);
            }
            uint32_t* dst = sA + r * FSTRIDE + c8 * 8;
            *(uint4*)(dst) = lo;       // 528B stride keeps 16B alignment
            *(uint4*)(dst + 4) = hi;
        }
        __syncthreads();

        float acc[16][4];
        #pragma unroll
        for (int i = 0; i < 16; i++)
            #pragma unroll
            for (int j = 0; j < 4; j++) acc[i][j] = 0.f;

        const uint32_t* pAr = sA + (w * 16 + qr) * FSTRIDE + qc;
        const uint32_t* pBr = sW + qr * FSTRIDE + qc;

        #pragma unroll 4
        for (int kk = 0; kk < 16; kk++) {
            const uint32_t* pA = pAr + kk * 8;
            uint32_t a0 = pA[0];
            uint32_t a1 = pA[8 * FSTRIDE];
            uint32_t a2 = pA[4];
            uint32_t a3 = pA[8 * FSTRIDE + 4];
            #pragma unroll
            for (int nb = 0; nb < 16; nb++) {
                const uint32_t* pB = pBr + nb * 8 * FSTRIDE + kk * 8;
                uint32_t b0 = pB[0];
                uint32_t b1 = pB[4];
                asm volatile(
                    "mma.sync.aligned.m16n8k8.row.col.f32.tf32.tf32.f32 "
                    "{%0,%1,%2,%3}, {%4,%5,%6,%7}, {%8,%9}, {%0,%1,%2,%3};"
                    : "+f"(acc[nb][0]), "+f"(acc[nb][1]),
                      "+f"(acc[nb][2]), "+f"(acc[nb][3])
                    : "r"(a0), "r"(a1), "r"(a2), "r"(a3), "r"(b0), "r"(b1));
            }
        }

        // epilogue: lane writes rows (w*16+qr) and (+8), cols nb*8+qc*2 (+1)
        int r_lo = row0 + w * 16 + qr;
        int r_hi = r_lo + 8;
        #pragma unroll
        for (int nb = 0; nb < 16; nb++) {
            int c = nb * 8 + qc * 2;
            if (r_lo < n) {
                float2* d = (float2*)&g_h[(size_t)r_lo * HID + c];
                *d = make_float2(acc[nb][0], acc[nb][1]);
            }
            if (r_hi < n) {
                float2* d = (float2*)&g_h[(size_t)r_hi * HID + c];
                *d = make_float2(acc[nb][2], acc[nb][3]);
            }
        }
        __syncthreads();
    }
}

// ---------------------------------------------------------------------------
// 6) destination-gather aggregation + fused BN stats (one warp per node)
__global__ void __launch_bounds__(256)
kk_aggstats(int n) {
    __shared__ float bsum[HID], bsq[HID];
    int t = threadIdx.x;
    int lane = t & 31;
    int w = t >> 5;
    if (t < HID) { bsum[t] = 0.f; bsq[t] = 0.f; }
    __syncthreads();

    int warp_id = blockIdx.x * 8 + w;
    int nwarps = gridDim.x * 8;

    float4 csum = make_float4(0.f, 0.f, 0.f, 0.f);
    float4 csq  = make_float4(0.f, 0.f, 0.f, 0.f);

    for (int node = warp_id; node < n; node += nwarps) {
        int start = g_off[node];
        int cnt   = g_deg[node];
        float dd  = g_dinv[node];

        float4 h4 = ((const float4*)(g_h + (size_t)node * HID))[lane];
        float4 acc = make_float4(dd * h4.x, dd * h4.y, dd * h4.z, dd * h4.w);

        int j = 0;
        for (; j + 2 <= cnt; j += 2) {
            int s0 = g_bsrc[start + j];
            int s1 = g_bsrc[start + j + 1];
            float d0 = g_dinv[s0];
            float d1 = g_dinv[s1];
            float4 a = ((const float4*)(g_h + (size_t)s0 * HID))[lane];
            float4 b = ((const float4*)(g_h + (size_t)s1 * HID))[lane];
            acc.x += d0 * a.x + d1 * b.x;
            acc.y += d0 * a.y + d1 * b.y;
            acc.z += d0 * a.z + d1 * b.z;
            acc.w += d0 * a.w + d1 * b.w;
        }
        if (j < cnt) {
            int s0 = g_bsrc[start + j];
            float d0 = g_dinv[s0];
            float4 a = ((const float4*)(g_h + (size_t)s0 * HID))[lane];
            acc.x += d0 * a.x; acc.y += d0 * a.y;
            acc.z += d0 * a.z; acc.w += d0 * a.w;
        }

        float4 agg4 = make_float4(dd * acc.x, dd * acc.y, dd * acc.z, dd * acc.w);
        ((float4*)(g_agg + (size_t)node * HID))[lane] = agg4;

        csum.x += agg4.x; csum.y += agg4.y; csum.z += agg4.z; csum.w += agg4.w;
        csq.x += agg4.x * agg4.x; csq.y += agg4.y * agg4.y;
        csq.z += agg4.z * agg4.z; csq.w += agg4.w * agg4.w;
    }

    atomicAdd(&bsum[lane * 4 + 0], csum.x);
    atomicAdd(&bsum[lane * 4 + 1], csum.y);
    atomicAdd(&bsum[lane * 4 + 2], csum.z);
    atomicAdd(&bsum[lane * 4 + 3], csum.w);
    atomicAdd(&bsq[lane * 4 + 0], csq.x);
    atomicAdd(&bsq[lane * 4 + 1], csq.y);
    atomicAdd(&bsq[lane * 4 + 2], csq.z);
    atomicAdd(&bsq[lane * 4 + 3], csq.w);
    __syncthreads();
    if (t < HID) {
        atomicAdd(&g_colsum[t], bsum[t]);
        atomicAdd(&g_colsq[t], bsq[t]);
    }
}

// 7) finalize BN coefficients (conv bias b cancels)
__global__ void kk_finstats(const float* __restrict__ gamma,
                            const float* __restrict__ beta, float inv_n) {
    int c = threadIdx.x;
    float mean = g_colsum[c] * inv_n;
    float var = g_colsq[c] * inv_n - mean * mean;
    float sc = gamma[c] * rsqrtf(var + 1e-5f);
    g_scale[c] = sc;
    g_shift[c] = beta[c] - sc * mean;
}

// 8) out = scale[c]*agg + shift[c]
__global__ void kk_out(float* __restrict__ out, int n) {
    size_t i = (size_t)blockIdx.x * blockDim.x + threadIdx.x;
    if (i >= (size_t)n * 32) return;
    int c4 = (int)(i & 31);
    float4 v = ((const float4*)g_agg)[i];
    float4 sc = ((const float4*)g_scale)[c4];
    float4 sh = ((const float4*)g_shift)[c4];
    v.x = fmaf(v.x, sc.x, sh.x);
    v.y = fmaf(v.y, sc.y, sh.y);
    v.z = fmaf(v.z, sc.z, sh.z);
    v.w = fmaf(v.w, sc.w, sh.w);
    ((float4*)out)[i] = v;
}

// ---------------------------------------------------------------------------
extern "C" void kernel_launch(void* const* d_in, const int* in_sizes, int n_in,
                              void* d_out, int out_size) {
    const float* x = (const float*)d_in[0];
    const int* ei = (const int*)d_in[1];          // int32 (JAX x64 disabled)
    const float* W = (const float*)d_in[2];
    const float* gamma = (const float*)d_in[4];
    const float* beta = (const float*)d_in[5];
    float* out = (float*)d_out;

    int n = in_sizes[0] / HID;
    int e = in_sizes[1] / 2;
    const int* erow = ei;
    const int* ecol = ei + e;

    int nb = (n + SCAN_BS - 1) / SCAN_BS;

    kk_init<<<(n + 255) / 256, 256>>>(n);
    kk_deg<<<(e + 255) / 256, 256>>>(ecol, e);
    kk_scan1<<<nb, SCAN_BS>>>(n);
    kk_scan2<<<1, MAX_SB>>>(nb);
    kk_scan3<<<nb, SCAN_BS>>>(n);
    kk_scatter<<<(e + 255) / 256, 256>>>(erow, ecol, e);

    {
        cudaFuncSetAttribute(kk_gemm, cudaFuncAttributeMaxDynamicSharedMemorySize,
                             SM_TOT);
        int need = (n + 63) / 64;
        int blocks = need < 296 ? need : 296;  // persistent, 2 CTAs/SM
        kk_gemm<<<blocks, 128, SM_TOT>>>(x, W, n);
    }

    kk_aggstats<<<1184, 256>>>(n);
    kk_finstats<<<1, HID>>>(gamma, beta, 1.0f / (float)n);

    {
        size_t total = (size_t)n * 32;
        kk_out<<<(int)((total + 255) / 256), 256>>>(out, n);
    }
}

// round 10
// speedup vs baseline: 2.6366x; 1.0462x over previous
#include <cuda_runtime.h>
#include <cuda_bf16.h>
#include <math.h>
#include <stdint.h>

#define HID 128
#define MAX_N 100000
#define MAX_E 600000
#define SCAN_BS 256

// Scratch (device globals: no allocation allowed in kernel_launch)
__device__ __align__(16) float g_h[MAX_N * HID];     // relu(x) @ W
__device__ __align__(16) float g_agg[MAX_N * HID];   // aggregated messages
__device__ int   g_deg[MAX_N];
__device__ int   g_off[MAX_N];
__device__ int   g_cursor[MAX_N];
__device__ int   g_bsrc[MAX_E];
__device__ int   g_total;
__device__ float g_dinv[MAX_N];
__device__ __align__(16) float g_colsum[HID];
__device__ __align__(16) float g_colsq[HID];
__device__ __align__(16) float g_scale[HID];
__device__ __align__(16) float g_shift[HID];

__device__ __forceinline__ uint32_t f2tf32(float f) {
    uint32_t r;
    asm("cvt.rna.tf32.f32 %0, %1;" : "=r"(r) : "f"(f));
    return r;
}

// ---------------------------------------------------------------------------
// 1) init
__global__ void kk_init(int n) {
    int i = blockIdx.x * blockDim.x + threadIdx.x;
    if (i < n) { g_deg[i] = 0; g_cursor[i] = 0; }
    if (i < HID) { g_colsum[i] = 0.f; g_colsq[i] = 0.f; }
    if (i == 0) g_total = 0;
}

// 2) in-degree from targets (edge_index is int32)
__global__ void kk_deg(const int* __restrict__ col, int e) {
    int i = blockIdx.x * blockDim.x + threadIdx.x;
    if (i < e) atomicAdd(&g_deg[col[i]], 1);
}

// 3) single-pass offset allocation: block-local scan + atomic bump base.
//    Bucket order across blocks is arbitrary — doesn't matter.
__global__ void kk_allocscan(int n) {
    __shared__ int sd[SCAN_BS];
    __shared__ int sbase;
    int t = threadIdx.x;
    int idx = blockIdx.x * SCAN_BS + t;
    int v = (idx < n) ? g_deg[idx] : 0;
    if (idx < n) g_dinv[idx] = rsqrtf((float)(v + 1));
    sd[t] = v;
    __syncthreads();
    #pragma unroll
    for (int s = 1; s < SCAN_BS; s <<= 1) {
        int x = (t >= s) ? sd[t - s] : 0;
        __syncthreads();
        sd[t] += x;
        __syncthreads();
    }
    if (t == SCAN_BS - 1) sbase = atomicAdd(&g_total, sd[t]);
    __syncthreads();
    if (idx < n) g_off[idx] = sbase + sd[t] - v;
}

// 4) scatter edges into destination buckets
__global__ void kk_scatter(const int* __restrict__ rows,
                           const int* __restrict__ cols, int e) {
    int i = blockIdx.x * blockDim.x + threadIdx.x;
    if (i >= e) return;
    int c = cols[i];
    int p = atomicAdd(&g_cursor[c], 1);
    g_bsrc[g_off[c] + p] = rows[i];
}

// ---------------------------------------------------------------------------
// 5) h = relu(x) @ W via tf32 mma.sync (m16n8k8), B-stationary.
//    128 threads (4 warps). Warp w owns COLUMN strip w*32..w*32+31.
//    B fragments (W^T) loaded ONCE per CTA into 128 regs; tiles stream 32 rows.
#define FSTRIDE 132                       // floats per smem row (128+4 pad)
#define SM_TOT (128 * FSTRIDE * 4)        // 67584 B (W staging; reused for x)

__global__ void __launch_bounds__(128, 2)
kk_gemm(const float* __restrict__ x, const float* __restrict__ W, int n) {
    extern __shared__ uint32_t sm[];
    int t = threadIdx.x;
    int w = t >> 5, lane = t & 31;
    int qr = lane >> 2;          // 0..7
    int qc = lane & 3;           // 0..3

    // stage W^T: sm[nn][k] = tf32(W[k*128 + nn])
    for (int k = 0; k < HID; k++)
        sm[t * FSTRIDE + k] = f2tf32(W[k * HID + t]);
    __syncthreads();

    // hoist B fragments: n = w*32 + nb*8 + qr, k = kk*8 + qc (+4)
    uint32_t bf[16][4][2];
    #pragma unroll
    for (int kk = 0; kk < 16; kk++)
        #pragma unroll
        for (int nb = 0; nb < 4; nb++) {
            const uint32_t* p = sm + (w * 32 + nb * 8 + qr) * FSTRIDE + kk * 8 + qc;
            bf[kk][nb][0] = p[0];
            bf[kk][nb][1] = p[4];
        }
    __syncthreads();   // done with W staging; reuse sm rows 0..31 for x tile

    for (int row0 = blockIdx.x * 32; row0 < n; row0 += gridDim.x * 32) {
        int rmax = min(32, n - row0);
        // load 32x128 x tile -> tf32 smem with ReLU (4 iters x 8 cols/thread)
        #pragma unroll
        for (int it = 0; it < 4; it++) {
            int idx = t + it * 128;           // 0..511
            int r = idx >> 4, c8 = idx & 15;
            uint4 lo, hi;
            if (r < rmax) {
                const float4* src =
                    (const float4*)&x[(size_t)(row0 + r) * HID + c8 * 8];
                float4 a = src[0], b = src[1];
                lo = make_uint4(f2tf32(fmaxf(a.x, 0.f)), f2tf32(fmaxf(a.y, 0.f)),
                                f2tf32(fmaxf(a.z, 0.f)), f2tf32(fmaxf(a.w, 0.f)));
                hi = make_uint4(f2tf32(fmaxf(b.x, 0.f)), f2tf32(fmaxf(b.y, 0.f)),
                                f2tf32(fmaxf(b.z, 0.f)), f2tf32(fmaxf(b.w, 0.f)));
            } else {
                lo = make_uint4(0, 0, 0, 0);
                hi = make_uint4(0, 0, 0, 0);
            }
            uint32_t* dst = sm + r * FSTRIDE + c8 * 8;
            *(uint4*)(dst) = lo;
            *(uint4*)(dst + 4) = hi;
        }
        __syncthreads();

        float acc[2][4][4];
        #pragma unroll
        for (int rg = 0; rg < 2; rg++)
            #pragma unroll
            for (int nb = 0; nb < 4; nb++)
                #pragma unroll
                for (int j = 0; j < 4; j++) acc[rg][nb][j] = 0.f;

        #pragma unroll
        for (int kk = 0; kk < 16; kk++) {
            #pragma unroll
            for (int rg = 0; rg < 2; rg++) {
                const uint32_t* pA = sm + (rg * 16 + qr) * FSTRIDE + kk * 8 + qc;
                uint32_t a0 = pA[0];
                uint32_t a1 = pA[8 * FSTRIDE];
                uint32_t a2 = pA[4];
                uint32_t a3 = pA[8 * FSTRIDE + 4];
                #pragma unroll
                for (int nb = 0; nb < 4; nb++) {
                    asm volatile(
                        "mma.sync.aligned.m16n8k8.row.col.f32.tf32.tf32.f32 "
                        "{%0,%1,%2,%3}, {%4,%5,%6,%7}, {%8,%9}, {%0,%1,%2,%3};"
                        : "+f"(acc[rg][nb][0]), "+f"(acc[rg][nb][1]),
                          "+f"(acc[rg][nb][2]), "+f"(acc[rg][nb][3])
                        : "r"(a0), "r"(a1), "r"(a2), "r"(a3),
                          "r"(bf[kk][nb][0]), "r"(bf[kk][nb][1]));
                }
            }
        }

        // epilogue: rows row0+rg*16+qr (+8), cols w*32+nb*8+qc*2 (+1)
        #pragma unroll
        for (int rg = 0; rg < 2; rg++) {
            int r_lo = row0 + rg * 16 + qr;
            int r_hi = r_lo + 8;
            #pragma unroll
            for (int nb = 0; nb < 4; nb++) {
                int c = w * 32 + nb * 8 + qc * 2;
                if (r_lo < n)
                    *(float2*)&g_h[(size_t)r_lo * HID + c] =
                        make_float2(acc[rg][nb][0], acc[rg][nb][1]);
                if (r_hi < n)
                    *(float2*)&g_h[(size_t)r_hi * HID + c] =
                        make_float2(acc[rg][nb][2], acc[rg][nb][3]);
            }
        }
        __syncthreads();
    }
}

// ---------------------------------------------------------------------------
// 6) destination-gather aggregation + fused BN stats (one warp per node)
__global__ void __launch_bounds__(256)
kk_aggstats(int n) {
    __shared__ float bsum[HID], bsq[HID];
    int t = threadIdx.x;
    int lane = t & 31;
    int w = t >> 5;
    if (t < HID) { bsum[t] = 0.f; bsq[t] = 0.f; }
    __syncthreads();

    int warp_id = blockIdx.x * 8 + w;
    int nwarps = gridDim.x * 8;

    float4 csum = make_float4(0.f, 0.f, 0.f, 0.f);
    float4 csq  = make_float4(0.f, 0.f, 0.f, 0.f);

    for (int node = warp_id; node < n; node += nwarps) {
        int start = g_off[node];
        int cnt   = g_deg[node];
        float dd  = g_dinv[node];

        float4 h4 = ((const float4*)(g_h + (size_t)node * HID))[lane];
        float4 acc = make_float4(dd * h4.x, dd * h4.y, dd * h4.z, dd * h4.w);

        int j = 0;
        for (; j + 2 <= cnt; j += 2) {
            int s0 = g_bsrc[start + j];
            int s1 = g_bsrc[start + j + 1];
            float d0 = g_dinv[s0];
            float d1 = g_dinv[s1];
            float4 a = ((const float4*)(g_h + (size_t)s0 * HID))[lane];
            float4 b = ((const float4*)(g_h + (size_t)s1 * HID))[lane];
            acc.x += d0 * a.x + d1 * b.x;
            acc.y += d0 * a.y + d1 * b.y;
            acc.z += d0 * a.z + d1 * b.z;
            acc.w += d0 * a.w + d1 * b.w;
        }
        if (j < cnt) {
            int s0 = g_bsrc[start + j];
            float d0 = g_dinv[s0];
            float4 a = ((const float4*)(g_h + (size_t)s0 * HID))[lane];
            acc.x += d0 * a.x; acc.y += d0 * a.y;
            acc.z += d0 * a.z; acc.w += d0 * a.w;
        }

        float4 agg4 = make_float4(dd * acc.x, dd * acc.y, dd * acc.z, dd * acc.w);
        ((float4*)(g_agg + (size_t)node * HID))[lane] = agg4;

        csum.x += agg4.x; csum.y += agg4.y; csum.z += agg4.z; csum.w += agg4.w;
        csq.x += agg4.x * agg4.x; csq.y += agg4.y * agg4.y;
        csq.z += agg4.z * agg4.z; csq.w += agg4.w * agg4.w;
    }

    atomicAdd(&bsum[lane * 4 + 0], csum.x);
    atomicAdd(&bsum[lane * 4 + 1], csum.y);
    atomicAdd(&bsum[lane * 4 + 2], csum.z);
    atomicAdd(&bsum[lane * 4 + 3], csum.w);
    atomicAdd(&bsq[lane * 4 + 0], csq.x);
    atomicAdd(&bsq[lane * 4 + 1], csq.y);
    atomicAdd(&bsq[lane * 4 + 2], csq.z);
    atomicAdd(&bsq[lane * 4 + 3], csq.w);
    __syncthreads();
    if (t < HID) {
        atomicAdd(&g_colsum[t], bsum[t]);
        atomicAdd(&g_colsq[t], bsq[t]);
    }
}

// 7) finalize BN coefficients (conv bias b cancels)
__global__ void kk_finstats(const float* __restrict__ gamma,
                            const float* __restrict__ beta, float inv_n) {
    int c = threadIdx.x;
    float mean = g_colsum[c] * inv_n;
    float var = g_colsq[c] * inv_n - mean * mean;
    float sc = gamma[c] * rsqrtf(var + 1e-5f);
    g_scale[c] = sc;
    g_shift[c] = beta[c] - sc * mean;
}

// 8) out = scale[c]*agg + shift[c]
__global__ void kk_out(float* __restrict__ out, int n) {
    size_t i = (size_t)blockIdx.x * blockDim.x + threadIdx.x;
    if (i >= (size_t)n * 32) return;
    int c4 = (int)(i & 31);
    float4 v = ((const float4*)g_agg)[i];
    float4 sc = ((const float4*)g_scale)[c4];
    float4 sh = ((const float4*)g_shift)[c4];
    v.x = fmaf(v.x, sc.x, sh.x);
    v.y = fmaf(v.y, sc.y, sh.y);
    v.z = fmaf(v.z, sc.z, sh.z);
    v.w = fmaf(v.w, sc.w, sh.w);
    ((float4*)out)[i] = v;
}

// ---------------------------------------------------------------------------
extern "C" void kernel_launch(void* const* d_in, const int* in_sizes, int n_in,
                              void* d_out, int out_size) {
    const float* x = (const float*)d_in[0];
    const int* ei = (const int*)d_in[1];          // int32 (JAX x64 disabled)
    const float* W = (const float*)d_in[2];
    const float* gamma = (const float*)d_in[4];
    const float* beta = (const float*)d_in[5];
    float* out = (float*)d_out;

    int n = in_sizes[0] / HID;
    int e = in_sizes[1] / 2;
    const int* erow = ei;
    const int* ecol = ei + e;

    int nb = (n + SCAN_BS - 1) / SCAN_BS;

    kk_init<<<(n + 255) / 256, 256>>>(n);
    kk_deg<<<(e + 255) / 256, 256>>>(ecol, e);
    kk_allocscan<<<nb, SCAN_BS>>>(n);
    kk_scatter<<<(e + 255) / 256, 256>>>(erow, ecol, e);

    {
        cudaFuncSetAttribute(kk_gemm, cudaFuncAttributeMaxDynamicSharedMemorySize,
                             SM_TOT);
        int need = (n + 31) / 32;
        int blocks = need < 296 ? need : 296;  // persistent, 2 CTAs/SM
        kk_gemm<<<blocks, 128, SM_TOT>>>(x, W, n);
    }

    kk_aggstats<<<1184, 256>>>(n);
    kk_finstats<<<1, HID>>>(gamma, beta, 1.0f / (float)n);

    {
        size_t total = (size_t)n * 32;
        kk_out<<<(int)((total + 255) / 256), 256>>>(out, n);
    }
}

// round 11
// speedup vs baseline: 3.0262x; 1.1478x over previous
#include <cuda_runtime.h>
#include <cuda_fp16.h>
#include <math.h>
#include <stdint.h>

#define HID 128
#define MAX_N 100000
#define MAX_E 600000
#define SCAN_BS 256

// Scratch (device globals: no allocation allowed in kernel_launch)
__device__ __align__(16) float g_h[MAX_N * HID];     // relu(x) @ W
__device__ __align__(16) float g_agg[MAX_N * HID];   // aggregated messages
__device__ int   g_deg[MAX_N];
__device__ int   g_off[MAX_N];
__device__ int   g_cursor[MAX_N];
__device__ int   g_bsrc[MAX_E];
__device__ int   g_total;
__device__ float g_dinv[MAX_N];
__device__ __align__(16) float g_colsum[HID];
__device__ __align__(16) float g_colsq[HID];
__device__ __align__(16) float g_scale[HID];
__device__ __align__(16) float g_shift[HID];

// ---------------------------------------------------------------------------
// 1) init
__global__ void kk_init(int n) {
    int i = blockIdx.x * blockDim.x + threadIdx.x;
    if (i < n) { g_deg[i] = 0; g_cursor[i] = 0; }
    if (i < HID) { g_colsum[i] = 0.f; g_colsq[i] = 0.f; }
    if (i == 0) g_total = 0;
}

// 2) in-degree from targets (edge_index is int32)
__global__ void kk_deg(const int* __restrict__ col, int e) {
    int i = blockIdx.x * blockDim.x + threadIdx.x;
    if (i < e) atomicAdd(&g_deg[col[i]], 1);
}

// 3) single-pass offset allocation: block-local scan + atomic bump base.
__global__ void kk_allocscan(int n) {
    __shared__ int sd[SCAN_BS];
    __shared__ int sbase;
    int t = threadIdx.x;
    int idx = blockIdx.x * SCAN_BS + t;
    int v = (idx < n) ? g_deg[idx] : 0;
    if (idx < n) g_dinv[idx] = rsqrtf((float)(v + 1));
    sd[t] = v;
    __syncthreads();
    #pragma unroll
    for (int s = 1; s < SCAN_BS; s <<= 1) {
        int x = (t >= s) ? sd[t - s] : 0;
        __syncthreads();
        sd[t] += x;
        __syncthreads();
    }
    if (t == SCAN_BS - 1) sbase = atomicAdd(&g_total, sd[t]);
    __syncthreads();
    if (idx < n) g_off[idx] = sbase + sd[t] - v;
}

// 4) scatter edges into destination buckets
__global__ void kk_scatter(const int* __restrict__ rows,
                           const int* __restrict__ cols, int e) {
    int i = blockIdx.x * blockDim.x + threadIdx.x;
    if (i >= e) return;
    int c = cols[i];
    int p = atomicAdd(&g_cursor[c], 1);
    g_bsrc[g_off[c] + p] = rows[i];
}

// ---------------------------------------------------------------------------
// 5) h = relu(x) @ W via fp16 mma.sync (m16n8k16, fp32 accum), B-stationary.
//    128 threads (4 warps). Warp w owns COLUMN strip w*32..w*32+31.
//    B fragments (W^T, fp16) hoisted once per CTA (64 regs); 32-row tiles.
//    smem rows are 272 B (136 halves): conflict-free 4B fragment loads.
#define HROW 272                         // bytes per smem row (128*2 + 16 pad)
#define SM_TOT (128 * HROW)              // 34816 B (W staging; reused for x)

__global__ void __launch_bounds__(128, 3)
kk_gemm(const float* __restrict__ x, const float* __restrict__ W, int n) {
    extern __shared__ char sm[];
    int t = threadIdx.x;
    int w = t >> 5, lane = t & 31;
    int qr = lane >> 2;          // 0..7
    int qc = lane & 3;           // 0..3

    // stage W^T as fp16: sm[nn][k] = h(W[k*128 + nn])
    for (int k = 0; k < HID; k++)
        *(__half*)(sm + t * HROW + k * 2) = __float2half_rn(W[k * HID + t]);
    __syncthreads();

    // hoist B fragments: n = w*32 + nb*8 + qr, k = kk*16 + qc*2 (+8)
    uint32_t bf[8][4][2];
    #pragma unroll
    for (int kk = 0; kk < 8; kk++)
        #pragma unroll
        for (int nb = 0; nb < 4; nb++) {
            const char* p = sm + (w * 32 + nb * 8 + qr) * HROW + kk * 32 + qc * 4;
            bf[kk][nb][0] = *(const uint32_t*)p;
            bf[kk][nb][1] = *(const uint32_t*)(p + 16);
        }
    __syncthreads();   // W staging dead; reuse rows 0..31 for x tile

    for (int row0 = blockIdx.x * 32; row0 < n; row0 += gridDim.x * 32) {
        int rmax = min(32, n - row0);
        // load 32x128 x tile -> fp16 smem with ReLU (4 iters x 8 cols/thread)
        #pragma unroll
        for (int it = 0; it < 4; it++) {
            int idx = t + it * 128;           // 0..511
            int r = idx >> 4, c8 = idx & 15;
            uint4 pk;
            if (r < rmax) {
                const float4* src =
                    (const float4*)&x[(size_t)(row0 + r) * HID + c8 * 8];
                float4 a = src[0], b = src[1];
                __half2 h0 = __floats2half2_rn(fmaxf(a.x, 0.f), fmaxf(a.y, 0.f));
                __half2 h1 = __floats2half2_rn(fmaxf(a.z, 0.f), fmaxf(a.w, 0.f));
                __half2 h2 = __floats2half2_rn(fmaxf(b.x, 0.f), fmaxf(b.y, 0.f));
                __half2 h3 = __floats2half2_rn(fmaxf(b.z, 0.f), fmaxf(b.w, 0.f));
                pk = make_uint4(*(uint32_t*)&h0, *(uint32_t*)&h1,
                                *(uint32_t*)&h2, *(uint32_t*)&h3);
            } else {
                pk = make_uint4(0, 0, 0, 0);
            }
            *(uint4*)(sm + r * HROW + c8 * 16) = pk;  // 272 = 17*16, aligned
        }
        __syncthreads();

        float acc[2][4][4];
        #pragma unroll
        for (int rg = 0; rg < 2; rg++)
            #pragma unroll
            for (int nb = 0; nb < 4; nb++)
                #pragma unroll
                for (int j = 0; j < 4; j++) acc[rg][nb][j] = 0.f;

        #pragma unroll
        for (int kk = 0; kk < 8; kk++) {
            #pragma unroll
            for (int rg = 0; rg < 2; rg++) {
                const char* pA = sm + (rg * 16 + qr) * HROW + kk * 32 + qc * 4;
                uint32_t a0 = *(const uint32_t*)(pA);
                uint32_t a1 = *(const uint32_t*)(pA + 8 * HROW);
                uint32_t a2 = *(const uint32_t*)(pA + 16);
                uint32_t a3 = *(const uint32_t*)(pA + 8 * HROW + 16);
                #pragma unroll
                for (int nb = 0; nb < 4; nb++) {
                    asm volatile(
                        "mma.sync.aligned.m16n8k16.row.col.f32.f16.f16.f32 "
                        "{%0,%1,%2,%3}, {%4,%5,%6,%7}, {%8,%9}, {%0,%1,%2,%3};"
                        : "+f"(acc[rg][nb][0]), "+f"(acc[rg][nb][1]),
                          "+f"(acc[rg][nb][2]), "+f"(acc[rg][nb][3])
                        : "r"(a0), "r"(a1), "r"(a2), "r"(a3),
                          "r"(bf[kk][nb][0]), "r"(bf[kk][nb][1]));
                }
            }
        }

        // epilogue: rows row0+rg*16+qr (+8), cols w*32+nb*8+qc*2 (+1)
        #pragma unroll
        for (int rg = 0; rg < 2; rg++) {
            int r_lo = row0 + rg * 16 + qr;
            int r_hi = r_lo + 8;
            #pragma unroll
            for (int nb = 0; nb < 4; nb++) {
                int c = w * 32 + nb * 8 + qc * 2;
                if (r_lo < n)
                    *(float2*)&g_h[(size_t)r_lo * HID + c] =
                        make_float2(acc[rg][nb][0], acc[rg][nb][1]);
                if (r_hi < n)
                    *(float2*)&g_h[(size_t)r_hi * HID + c] =
                        make_float2(acc[rg][nb][2], acc[rg][nb][3]);
            }
        }
        __syncthreads();
    }
}

// ---------------------------------------------------------------------------
// 6) destination-gather aggregation + fused BN stats (one warp per node)
__global__ void __launch_bounds__(256)
kk_aggstats(int n) {
    __shared__ float bsum[HID], bsq[HID];
    int t = threadIdx.x;
    int lane = t & 31;
    int w = t >> 5;
    if (t < HID) { bsum[t] = 0.f; bsq[t] = 0.f; }
    __syncthreads();

    int warp_id = blockIdx.x * 8 + w;
    int nwarps = gridDim.x * 8;

    float4 csum = make_float4(0.f, 0.f, 0.f, 0.f);
    float4 csq  = make_float4(0.f, 0.f, 0.f, 0.f);

    for (int node = warp_id; node < n; node += nwarps) {
        int start = g_off[node];
        int cnt   = g_deg[node];
        float dd  = g_dinv[node];

        float4 h4 = ((const float4*)(g_h + (size_t)node * HID))[lane];
        float4 acc = make_float4(dd * h4.x, dd * h4.y, dd * h4.z, dd * h4.w);

        int j = 0;
        for (; j + 2 <= cnt; j += 2) {
            int s0 = g_bsrc[start + j];
            int s1 = g_bsrc[start + j + 1];
            float d0 = g_dinv[s0];
            float d1 = g_dinv[s1];
            float4 a = ((const float4*)(g_h + (size_t)s0 * HID))[lane];
            float4 b = ((const float4*)(g_h + (size_t)s1 * HID))[lane];
            acc.x += d0 * a.x + d1 * b.x;
            acc.y += d0 * a.y + d1 * b.y;
            acc.z += d0 * a.z + d1 * b.z;
            acc.w += d0 * a.w + d1 * b.w;
        }
        if (j < cnt) {
            int s0 = g_bsrc[start + j];
            float d0 = g_dinv[s0];
            float4 a = ((const float4*)(g_h + (size_t)s0 * HID))[lane];
            acc.x += d0 * a.x; acc.y += d0 * a.y;
            acc.z += d0 * a.z; acc.w += d0 * a.w;
        }

        float4 agg4 = make_float4(dd * acc.x, dd * acc.y, dd * acc.z, dd * acc.w);
        ((float4*)(g_agg + (size_t)node * HID))[lane] = agg4;

        csum.x += agg4.x; csum.y += agg4.y; csum.z += agg4.z; csum.w += agg4.w;
        csq.x += agg4.x * agg4.x; csq.y += agg4.y * agg4.y;
        csq.z += agg4.z * agg4.z; csq.w += agg4.w * agg4.w;
    }

    atomicAdd(&bsum[lane * 4 + 0], csum.x);
    atomicAdd(&bsum[lane * 4 + 1], csum.y);
    atomicAdd(&bsum[lane * 4 + 2], csum.z);
    atomicAdd(&bsum[lane * 4 + 3], csum.w);
    atomicAdd(&bsq[lane * 4 + 0], csq.x);
    atomicAdd(&bsq[lane * 4 + 1], csq.y);
    atomicAdd(&bsq[lane * 4 + 2], csq.z);
    atomicAdd(&bsq[lane * 4 + 3], csq.w);
    __syncthreads();
    if (t < HID) {
        atomicAdd(&g_colsum[t], bsum[t]);
        atomicAdd(&g_colsq[t], bsq[t]);
    }
}

// 7) finalize BN coefficients (conv bias b cancels)
__global__ void kk_finstats(const float* __restrict__ gamma,
                            const float* __restrict__ beta, float inv_n) {
    int c = threadIdx.x;
    float mean = g_colsum[c] * inv_n;
    float var = g_colsq[c] * inv_n - mean * mean;
    float sc = gamma[c] * rsqrtf(var + 1e-5f);
    g_scale[c] = sc;
    g_shift[c] = beta[c] - sc * mean;
}

// 8) out = scale[c]*agg + shift[c]
__global__ void kk_out(float* __restrict__ out, int n) {
    size_t i = (size_t)blockIdx.x * blockDim.x + threadIdx.x;
    if (i >= (size_t)n * 32) return;
    int c4 = (int)(i & 31);
    float4 v = ((const float4*)g_agg)[i];
    float4 sc = ((const float4*)g_scale)[c4];
    float4 sh = ((const float4*)g_shift)[c4];
    v.x = fmaf(v.x, sc.x, sh.x);
    v.y = fmaf(v.y, sc.y, sh.y);
    v.z = fmaf(v.z, sc.z, sh.z);
    v.w = fmaf(v.w, sc.w, sh.w);
    ((float4*)out)[i] = v;
}

// ---------------------------------------------------------------------------
extern "C" void kernel_launch(void* const* d_in, const int* in_sizes, int n_in,
                              void* d_out, int out_size) {
    const float* x = (const float*)d_in[0];
    const int* ei = (const int*)d_in[1];          // int32 (JAX x64 disabled)
    const float* W = (const float*)d_in[2];
    const float* gamma = (const float*)d_in[4];
    const float* beta = (const float*)d_in[5];
    float* out = (float*)d_out;

    int n = in_sizes[0] / HID;
    int e = in_sizes[1] / 2;
    const int* erow = ei;
    const int* ecol = ei + e;

    int nb = (n + SCAN_BS - 1) / SCAN_BS;

    kk_init<<<(n + 255) / 256, 256>>>(n);
    kk_deg<<<(e + 255) / 256, 256>>>(ecol, e);
    kk_allocscan<<<nb, SCAN_BS>>>(n);
    kk_scatter<<<(e + 255) / 256, 256>>>(erow, ecol, e);

    {
        cudaFuncSetAttribute(kk_gemm, cudaFuncAttributeMaxDynamicSharedMemorySize,
                             SM_TOT);
        int need = (n + 31) / 32;
        int blocks = need < 444 ? need : 444;  // persistent, 3 CTAs/SM
        kk_gemm<<<blocks, 128, SM_TOT>>>(x, W, n);
    }

    kk_aggstats<<<1184, 256>>>(n);
    kk_finstats<<<1, HID>>>(gamma, beta, 1.0f / (float)n);

    {
        size_t total = (size_t)n * 32;
        kk_out<<<(int)((total + 255) / 256), 256>>>(out, n);
    }
}

// round 12
// speedup vs baseline: 3.3703x; 1.1137x over previous
#include <cuda_runtime.h>
#include <cuda_fp16.h>
#include <math.h>
#include <stdint.h>

#define HID 128
#define MAX_N 100000
#define MAX_E 600000
#define SCAN_BS 256

// Scratch (device globals: no allocation allowed in kernel_launch)
__device__ __align__(16) __half g_h2[MAX_N * HID];   // fp16( dinv[row] * (relu(x)@W) )
__device__ __align__(16) float g_agg[MAX_N * HID];   // aggregated messages
__device__ int   g_deg[MAX_N];
__device__ int   g_off[MAX_N];
__device__ int   g_cursor[MAX_N];
__device__ int   g_bsrc[MAX_E];
__device__ int   g_total;
__device__ float g_dinv[MAX_N];
__device__ __align__(16) float g_colsum[HID];
__device__ __align__(16) float g_colsq[HID];

// ---------------------------------------------------------------------------
// 1) init
__global__ void kk_init(int n) {
    int i = blockIdx.x * blockDim.x + threadIdx.x;
    if (i < n) { g_deg[i] = 0; g_cursor[i] = 0; }
    if (i < HID) { g_colsum[i] = 0.f; g_colsq[i] = 0.f; }
    if (i == 0) g_total = 0;
}

// 2) in-degree from targets (edge_index is int32)
__global__ void kk_deg(const int* __restrict__ col, int e) {
    int i = blockIdx.x * blockDim.x + threadIdx.x;
    if (i < e) atomicAdd(&g_deg[col[i]], 1);
}

// 3) single-pass offset allocation: block-local scan + atomic bump base.
__global__ void kk_allocscan(int n) {
    __shared__ int sd[SCAN_BS];
    __shared__ int sbase;
    int t = threadIdx.x;
    int idx = blockIdx.x * SCAN_BS + t;
    int v = (idx < n) ? g_deg[idx] : 0;
    if (idx < n) g_dinv[idx] = rsqrtf((float)(v + 1));
    sd[t] = v;
    __syncthreads();
    #pragma unroll
    for (int s = 1; s < SCAN_BS; s <<= 1) {
        int x = (t >= s) ? sd[t - s] : 0;
        __syncthreads();
        sd[t] += x;
        __syncthreads();
    }
    if (t == SCAN_BS - 1) sbase = atomicAdd(&g_total, sd[t]);
    __syncthreads();
    if (idx < n) g_off[idx] = sbase + sd[t] - v;
}

// 4) scatter edges into destination buckets
__global__ void kk_scatter(const int* __restrict__ rows,
                           const int* __restrict__ cols, int e) {
    int i = blockIdx.x * blockDim.x + threadIdx.x;
    if (i >= e) return;
    int c = cols[i];
    int p = atomicAdd(&g_cursor[c], 1);
    g_bsrc[g_off[c] + p] = rows[i];
}

// ---------------------------------------------------------------------------
// 5) h2 = fp16(dinv * (relu(x) @ W)) via fp16 mma.sync m16n8k16, B-stationary.
//    128 threads (4 warps). Warp w owns COLUMN strip w*32..w*32+31.
#define HROW 272                         // bytes per smem row (128*2 + 16 pad)
#define SM_TOT (128 * HROW)              // 34816 B (W staging; reused for x)

__global__ void __launch_bounds__(128, 3)
kk_gemm(const float* __restrict__ x, const float* __restrict__ W, int n) {
    extern __shared__ char sm[];
    int t = threadIdx.x;
    int w = t >> 5, lane = t & 31;
    int qr = lane >> 2;          // 0..7
    int qc = lane & 3;           // 0..3

    // stage W^T as fp16: sm[nn][k] = h(W[k*128 + nn])
    for (int k = 0; k < HID; k++)
        *(__half*)(sm + t * HROW + k * 2) = __float2half_rn(W[k * HID + t]);
    __syncthreads();

    // hoist B fragments: n = w*32 + nb*8 + qr, k = kk*16 + qc*2 (+8)
    uint32_t bf[8][4][2];
    #pragma unroll
    for (int kk = 0; kk < 8; kk++)
        #pragma unroll
        for (int nb = 0; nb < 4; nb++) {
            const char* p = sm + (w * 32 + nb * 8 + qr) * HROW + kk * 32 + qc * 4;
            bf[kk][nb][0] = *(const uint32_t*)p;
            bf[kk][nb][1] = *(const uint32_t*)(p + 16);
        }
    __syncthreads();   // W staging dead; reuse rows 0..31 for x tile

    for (int row0 = blockIdx.x * 32; row0 < n; row0 += gridDim.x * 32) {
        int rmax = min(32, n - row0);
        // load 32x128 x tile -> fp16 smem with ReLU (4 iters x 8 cols/thread)
        #pragma unroll
        for (int it = 0; it < 4; it++) {
            int idx = t + it * 128;           // 0..511
            int r = idx >> 4, c8 = idx & 15;
            uint4 pk;
            if (r < rmax) {
                const float4* src =
                    (const float4*)&x[(size_t)(row0 + r) * HID + c8 * 8];
                float4 a = src[0], b = src[1];
                __half2 h0 = __floats2half2_rn(fmaxf(a.x, 0.f), fmaxf(a.y, 0.f));
                __half2 h1 = __floats2half2_rn(fmaxf(a.z, 0.f), fmaxf(a.w, 0.f));
                __half2 h2 = __floats2half2_rn(fmaxf(b.x, 0.f), fmaxf(b.y, 0.f));
                __half2 h3 = __floats2half2_rn(fmaxf(b.z, 0.f), fmaxf(b.w, 0.f));
                pk = make_uint4(*(uint32_t*)&h0, *(uint32_t*)&h1,
                                *(uint32_t*)&h2, *(uint32_t*)&h3);
            } else {
                pk = make_uint4(0, 0, 0, 0);
            }
            *(uint4*)(sm + r * HROW + c8 * 16) = pk;  // 272 = 17*16, aligned
        }
        __syncthreads();

        float acc[2][4][4];
        #pragma unroll
        for (int rg = 0; rg < 2; rg++)
            #pragma unroll
            for (int nb = 0; nb < 4; nb++)
                #pragma unroll
                for (int j = 0; j < 4; j++) acc[rg][nb][j] = 0.f;

        #pragma unroll
        for (int kk = 0; kk < 8; kk++) {
            #pragma unroll
            for (int rg = 0; rg < 2; rg++) {
                const char* pA = sm + (rg * 16 + qr) * HROW + kk * 32 + qc * 4;
                uint32_t a0 = *(const uint32_t*)(pA);
                uint32_t a1 = *(const uint32_t*)(pA + 8 * HROW);
                uint32_t a2 = *(const uint32_t*)(pA + 16);
                uint32_t a3 = *(const uint32_t*)(pA + 8 * HROW + 16);
                #pragma unroll
                for (int nb = 0; nb < 4; nb++) {
                    asm volatile(
                        "mma.sync.aligned.m16n8k16.row.col.f32.f16.f16.f32 "
                        "{%0,%1,%2,%3}, {%4,%5,%6,%7}, {%8,%9}, {%0,%1,%2,%3};"
                        : "+f"(acc[rg][nb][0]), "+f"(acc[rg][nb][1]),
                          "+f"(acc[rg][nb][2]), "+f"(acc[rg][nb][3])
                        : "r"(a0), "r"(a1), "r"(a2), "r"(a3),
                          "r"(bf[kk][nb][0]), "r"(bf[kk][nb][1]));
                }
            }
        }

        // epilogue: h2[row] = fp16(dinv[row] * acc). rows rg*16+qr (+8),
        // cols w*32+nb*8+qc*2 (+1); half2 stores (4B aligned).
        #pragma unroll
        for (int rg = 0; rg < 2; rg++) {
            int r_lo = row0 + rg * 16 + qr;
            int r_hi = r_lo + 8;
            float d_lo = (r_lo < n) ? g_dinv[r_lo] : 0.f;
            float d_hi = (r_hi < n) ? g_dinv[r_hi] : 0.f;
            #pragma unroll
            for (int nb = 0; nb < 4; nb++) {
                int c = w * 32 + nb * 8 + qc * 2;
                if (r_lo < n) {
                    __half2 hv = __floats2half2_rn(acc[rg][nb][0] * d_lo,
                                                   acc[rg][nb][1] * d_lo);
                    *(__half2*)&g_h2[(size_t)r_lo * HID + c] = hv;
                }
                if (r_hi < n) {
                    __half2 hv = __floats2half2_rn(acc[rg][nb][2] * d_hi,
                                                   acc[rg][nb][3] * d_hi);
                    *(__half2*)&g_h2[(size_t)r_hi * HID + c] = hv;
                }
            }
        }
        __syncthreads();
    }
}

// ---------------------------------------------------------------------------
// 6) destination-gather aggregation + fused BN stats (one warp per node).
//    agg[c] = dinv[c] * ( sum_src h2[src] + h2[c] )   (h2 pre-scaled by dinv)
__global__ void __launch_bounds__(256)
kk_aggstats(int n) {
    __shared__ float bsum[HID], bsq[HID];
    int t = threadIdx.x;
    int lane = t & 31;
    int w = t >> 5;
    if (t < HID) { bsum[t] = 0.f; bsq[t] = 0.f; }
    __syncthreads();

    int warp_id = blockIdx.x * 8 + w;
    int nwarps = gridDim.x * 8;

    float4 csum = make_float4(0.f, 0.f, 0.f, 0.f);
    float4 csq  = make_float4(0.f, 0.f, 0.f, 0.f);

    for (int node = warp_id; node < n; node += nwarps) {
        int start = g_off[node];
        int cnt   = g_deg[node];
        float dd  = g_dinv[node];

        // lane owns cols lane*4..lane*4+3 -> uint2 (4 halves) at index lane
        uint2 sv = ((const uint2*)(g_h2 + (size_t)node * HID))[lane];
        float2 f0 = __half22float2(*(__half2*)&sv.x);
        float2 f1 = __half22float2(*(__half2*)&sv.y);
        float4 acc = make_float4(f0.x, f0.y, f1.x, f1.y);  // self: h2[c]

        int j = 0;
        for (; j + 2 <= cnt; j += 2) {
            int s0 = g_bsrc[start + j];
            int s1 = g_bsrc[start + j + 1];
            uint2 a = ((const uint2*)(g_h2 + (size_t)s0 * HID))[lane];
            uint2 b = ((const uint2*)(g_h2 + (size_t)s1 * HID))[lane];
            float2 a0 = __half22float2(*(__half2*)&a.x);
            float2 a1 = __half22float2(*(__half2*)&a.y);
            float2 b0 = __half22float2(*(__half2*)&b.x);
            float2 b1 = __half22float2(*(__half2*)&b.y);
            acc.x += a0.x + b0.x;
            acc.y += a0.y + b0.y;
            acc.z += a1.x + b1.x;
            acc.w += a1.y + b1.y;
        }
        if (j < cnt) {
            int s0 = g_bsrc[start + j];
            uint2 a = ((const uint2*)(g_h2 + (size_t)s0 * HID))[lane];
            float2 a0 = __half22float2(*(__half2*)&a.x);
            float2 a1 = __half22float2(*(__half2*)&a.y);
            acc.x += a0.x; acc.y += a0.y;
            acc.z += a1.x; acc.w += a1.y;
        }

        float4 agg4 = make_float4(dd * acc.x, dd * acc.y, dd * acc.z, dd * acc.w);
        ((float4*)(g_agg + (size_t)node * HID))[lane] = agg4;

        csum.x += agg4.x; csum.y += agg4.y; csum.z += agg4.z; csum.w += agg4.w;
        csq.x += agg4.x * agg4.x; csq.y += agg4.y * agg4.y;
        csq.z += agg4.z * agg4.z; csq.w += agg4.w * agg4.w;
    }

    atomicAdd(&bsum[lane * 4 + 0], csum.x);
    atomicAdd(&bsum[lane * 4 + 1], csum.y);
    atomicAdd(&bsum[lane * 4 + 2], csum.z);
    atomicAdd(&bsum[lane * 4 + 3], csum.w);
    atomicAdd(&bsq[lane * 4 + 0], csq.x);
    atomicAdd(&bsq[lane * 4 + 1], csq.y);
    atomicAdd(&bsq[lane * 4 + 2], csq.z);
    atomicAdd(&bsq[lane * 4 + 3], csq.w);
    __syncthreads();
    if (t < HID) {
        atomicAdd(&g_colsum[t], bsum[t]);
        atomicAdd(&g_colsq[t], bsq[t]);
    }
}

// 7) out = scale[c]*agg + shift[c]; BN coefficients computed per block (cheap).
__global__ void __launch_bounds__(256)
kk_out(float* __restrict__ out, const float* __restrict__ gamma,
       const float* __restrict__ beta, float inv_n, int n) {
    __shared__ float ssc[HID], ssh[HID];
    int t = threadIdx.x;
    if (t < HID) {
        float mean = g_colsum[t] * inv_n;
        float var = g_colsq[t] * inv_n - mean * mean;
        float sc = gamma[t] * rsqrtf(var + 1e-5f);
        ssc[t] = sc;
        ssh[t] = beta[t] - sc * mean;
    }
    __syncthreads();

    size_t total = (size_t)n * 32;
    for (size_t i = (size_t)blockIdx.x * blockDim.x + t; i < total;
         i += (size_t)gridDim.x * blockDim.x) {
        int c4 = (int)(i & 31);
        float4 v = ((const float4*)g_agg)[i];
        float4 sc = *(const float4*)&ssc[c4 * 4];
        float4 sh = *(const float4*)&ssh[c4 * 4];
        v.x = fmaf(v.x, sc.x, sh.x);
        v.y = fmaf(v.y, sc.y, sh.y);
        v.z = fmaf(v.z, sc.z, sh.z);
        v.w = fmaf(v.w, sc.w, sh.w);
        ((float4*)out)[i] = v;
    }
}

// ---------------------------------------------------------------------------
extern "C" void kernel_launch(void* const* d_in, const int* in_sizes, int n_in,
                              void* d_out, int out_size) {
    const float* x = (const float*)d_in[0];
    const int* ei = (const int*)d_in[1];          // int32 (JAX x64 disabled)
    const float* W = (const float*)d_in[2];
    const float* gamma = (const float*)d_in[4];
    const float* beta = (const float*)d_in[5];
    float* out = (float*)d_out;

    int n = in_sizes[0] / HID;
    int e = in_sizes[1] / 2;
    const int* erow = ei;
    const int* ecol = ei + e;

    int nb = (n + SCAN_BS - 1) / SCAN_BS;

    kk_init<<<(n + 255) / 256, 256>>>(n);
    kk_deg<<<(e + 255) / 256, 256>>>(ecol, e);
    kk_allocscan<<<nb, SCAN_BS>>>(n);
    kk_scatter<<<(e + 255) / 256, 256>>>(erow, ecol, e);

    {
        cudaFuncSetAttribute(kk_gemm, cudaFuncAttributeMaxDynamicSharedMemorySize,
                             SM_TOT);
        int need = (n + 31) / 32;
        int blocks = need < 444 ? need : 444;  // persistent, 3 CTAs/SM
        kk_gemm<<<blocks, 128, SM_TOT>>>(x, W, n);
    }

    kk_aggstats<<<1184, 256>>>(n);
    kk_out<<<2048, 256>>>(out, gamma, beta, 1.0f / (float)n, n);
}